// round 1
// baseline (speedup 1.0000x reference)
#include <cuda_runtime.h>
#include <math.h>

// Problem shape (fixed by setup_inputs): B=64, H=W=24, D=1024, S=577
#define B_   64
#define H_   24
#define W_   24
#define D_   1024
#define S_   (1 + H_*W_)          // 577
#define SD_  (S_ * D_)            // 590848
#define SD4_ (SD_ / 4)            // 147712

#define OMEGA1 2.62205755429212
#define LIM_T  5000.0f
#define LIM_WP 10000.0f
#define NEAR_  1.5e-7f

// Positional table scratch: [S, D] floats (already scaled by pos_scale)
__device__ float g_pos[SD_];

__device__ __forceinline__ float block_reduce_sum(float v, float* sh) {
    // 256 threads = 8 warps
    #pragma unroll
    for (int o = 16; o > 0; o >>= 1) v += __shfl_down_sync(0xffffffffu, v, o);
    int w = threadIdx.x >> 5, l = threadIdx.x & 31;
    if (l == 0) sh[w] = v;
    __syncthreads();
    if (w == 0) {
        v = (l < 8) ? sh[l] : 0.0f;
        #pragma unroll
        for (int o = 4; o > 0; o >>= 1) v += __shfl_down_sync(0xffffffffu, v, o);
        if (l == 0) sh[0] = v;
    }
    __syncthreads();
    float r = sh[0];
    __syncthreads();
    return r;
}

__global__ __launch_bounds__(256)
void build_pos_kernel(const float* __restrict__ log_alpha_scale,
                      const float* __restrict__ alpha_learn,
                      const float* __restrict__ proj_w,   // [4, D]
                      const float* __restrict__ proj_b,   // [D]
                      const float* __restrict__ ln_g,     // [D]
                      const float* __restrict__ ln_b,     // [D]
                      const float* __restrict__ cls_pos,  // [D]
                      const float* __restrict__ pos_scale)// [1]
{
    __shared__ float sh_red[32];
    __shared__ float sh_p[D_];
    __shared__ float sh_feats[4];

    const int row = blockIdx.x;      // 0 = cls, 1..576 = patches
    const int tid = threadIdx.x;
    const float pscale = pos_scale[0];

    if (row == 0) {
        for (int d = tid; d < D_; d += 256)
            g_pos[d] = cls_pos[d] * pscale;
        return;
    }

    const int idx = row - 1;
    const int pr = idx / W_;         // row index (v)
    const int pc = idx % W_;         // col index (u)

    // omega_3p = clip(softplus(alpha_learn), 0.02, 8.0)
    float al = alpha_learn[0];
    float sp = (al > 20.0f) ? al : log1pf(expf(al));
    float omega3p = fminf(fmaxf(sp, 0.02f), 8.0f);

    const float u = (pc + 0.5f) / (float)W_;
    const float v = (pr + 0.5f) / (float)H_;
    const float zr = u * (2.0f * (float)OMEGA1) * 0.4f;
    const float zi = v * (2.0f * omega3p) * 0.4f;

    // Lattice sum over m,n in [-12,12], excluding (0,0): 25*25-1 = 624 points
    float s1r = 0.f, s1i = 0.f, s2r = 0.f, s2i = 0.f;
    for (int k = tid; k < 625; k += 256) {
        int m = k / 25 - 12;
        int n = k % 25 - 12;
        if (m == 0 && n == 0) continue;
        float wr = 2.0f * (float)m * (float)OMEGA1;
        float wi = 2.0f * (float)n * (float)OMEGA1;
        float dr = zr - wr, di = zi - wi;
        float n2 = dr * dr + di * di;
        if (n2 <= NEAR_ * NEAR_) continue;   // mask (never active here)
        float inv  = 1.0f / n2;
        float inv2 = inv * inv;
        // 1/d^2 = conj(d^2)/n2^2
        float d2r = dr * dr - di * di;
        float d2i = 2.0f * dr * di;
        float t1r = d2r * inv2;
        float t1i = -d2i * inv2;
        // subtract 1/w^2
        float wn2 = wr * wr + wi * wi;
        float winv2 = 1.0f / (wn2 * wn2);
        t1r -= (wr * wr - wi * wi) * winv2;
        t1i -= -(2.0f * wr * wi) * winv2;
        // per-term clamp (matches reference; inactive in practice)
        t1r = fminf(fmaxf(t1r, -LIM_T), LIM_T);
        t1i = fminf(fmaxf(t1i, -LIM_T), LIM_T);
        // -2/d^3 = -2*conj(d^3)/n2^3
        float d3r = d2r * dr - d2i * di;
        float d3i = d2r * di + d2i * dr;
        float inv3 = inv2 * inv;
        float t2r = -2.0f * d3r * inv3;
        float t2i =  2.0f * d3i * inv3;
        t2r = fminf(fmaxf(t2r, -LIM_T), LIM_T);
        t2i = fminf(fmaxf(t2i, -LIM_T), LIM_T);
        s1r += t1r; s1i += t1i;
        s2r += t2r; s2i += t2i;
    }
    s1r = block_reduce_sum(s1r, sh_red);
    s1i = block_reduce_sum(s1i, sh_red);
    s2r = block_reduce_sum(s2r, sh_red);
    s2i = block_reduce_sum(s2i, sh_red);

    if (tid == 0) {
        float wpr, wpi, wppr, wppi;
        float zn2 = zr * zr + zi * zi;
        if (zn2 < NEAR_ * NEAR_) {
            wpr = 500.0f; wpi = 0.0f; wppr = 500.0f; wppi = 0.0f;
        } else {
            float zinv  = 1.0f / zn2;
            float zinv2 = zinv * zinv;
            float z2r = zr * zr - zi * zi;
            float z2i = 2.0f * zr * zi;
            wpr = z2r * zinv2 + s1r;
            wpi = -z2i * zinv2 + s1i;
            float z3r = z2r * zr - z2i * zi;
            float z3i = z2r * zi + z2i * zr;
            float zinv3 = zinv2 * zinv;
            wppr = -2.0f * z3r * zinv3 + s2r;
            wppi =  2.0f * z3i * zinv3 + s2i;
        }
        wpr  = fminf(fmaxf(wpr,  -LIM_WP), LIM_WP);
        wpi  = fminf(fmaxf(wpi,  -LIM_WP), LIM_WP);
        wppr = fminf(fmaxf(wppr, -LIM_WP), LIM_WP);
        wppi = fminf(fmaxf(wppi, -LIM_WP), LIM_WP);

        float alpha = fminf(fmaxf(expf(log_alpha_scale[0]), 0.002f), 0.8f);
        sh_feats[0] = tanhf(alpha * wpr);
        sh_feats[1] = tanhf(alpha * wpi);
        sh_feats[2] = tanhf(alpha * wppr);
        sh_feats[3] = tanhf(alpha * wppi);
    }
    __syncthreads();

    const float f0 = sh_feats[0], f1 = sh_feats[1], f2 = sh_feats[2], f3 = sh_feats[3];

    // p = feats @ proj_w + proj_b; accumulate sum and sumsq
    float lsum = 0.f, lsq = 0.f;
    for (int d = tid; d < D_; d += 256) {
        float p = f0 * proj_w[d] + f1 * proj_w[D_ + d]
                + f2 * proj_w[2 * D_ + d] + f3 * proj_w[3 * D_ + d]
                + proj_b[d];
        sh_p[d] = p;
        lsum += p;
        lsq  += p * p;
    }
    float tsum = block_reduce_sum(lsum, sh_red);
    float tsq  = block_reduce_sum(lsq,  sh_red);
    float mean = tsum * (1.0f / D_);
    float var  = tsq * (1.0f / D_) - mean * mean;
    float rstd = rsqrtf(var + 1e-5f);

    float* outrow = g_pos + row * D_;
    for (int d = tid; d < D_; d += 256) {
        float n = (sh_p[d] - mean) * rstd * ln_g[d] + ln_b[d];
        outrow[d] = n * pscale;
    }
}

__global__ __launch_bounds__(256)
void add_pos_kernel(const float4* __restrict__ x, float4* __restrict__ out)
{
    const int b = blockIdx.y;
    const int i = blockIdx.x * 256 + threadIdx.x;   // float4 index within a batch
    if (i >= SD4_) return;
    const long long gi = (long long)b * SD4_ + i;
    float4 xv = x[gi];
    float4 pv = reinterpret_cast<const float4*>(g_pos)[i];
    xv.x += pv.x; xv.y += pv.y; xv.z += pv.z; xv.w += pv.w;
    out[gi] = xv;
}

extern "C" void kernel_launch(void* const* d_in, const int* in_sizes, int n_in,
                              void* d_out, int out_size)
{
    // metadata order: x, h, w, log_alpha_scale, alpha_learn, proj_w, proj_b,
    //                 ln_g, ln_b, cls_pos, pos_scale
    const float* x    = (const float*)d_in[0];
    const float* las  = (const float*)d_in[3];
    const float* al   = (const float*)d_in[4];
    const float* pw   = (const float*)d_in[5];
    const float* pb   = (const float*)d_in[6];
    const float* lg   = (const float*)d_in[7];
    const float* lb   = (const float*)d_in[8];
    const float* cls  = (const float*)d_in[9];
    const float* psc  = (const float*)d_in[10];

    build_pos_kernel<<<S_, 256>>>(las, al, pw, pb, lg, lb, cls, psc);

    dim3 grid((SD4_ + 255) / 256, B_);
    add_pos_kernel<<<grid, 256>>>((const float4*)x, (float4*)d_out);
}